// round 15
// baseline (speedup 1.0000x reference)
#include <cuda_runtime.h>
#include <math.h>

#define NMAX 50000
#define EMAX 1600000

// ---------------- static device scratch ----------------
__device__ float g_fs[NMAX * 188];     // projected features fs (max F=188)
__device__ float g_act0[NMAX * 128];
__device__ float g_act1[NMAX * 128];
__device__ float g_out2[NMAX * 188];
__device__ float g_el[NMAX * 4];
__device__ float g_er[NMAX * 4];
__device__ int   g_csrc[EMAX];
__device__ int   g_rowptr[NMAX + 1];
__device__ int   g_cnt[NMAX];
__device__ int   g_cursor[NMAX];

__device__ __forceinline__ float lrelu(float x) { return x >= 0.f ? x : 0.2f * x; }

// ---- packed fp32x2 FMA (used in aggregation) ----
__device__ __forceinline__ void ffma2(unsigned long long& c, unsigned long long a,
                                      unsigned long long b) {
    asm("fma.rn.f32x2 %0, %1, %2, %0;" : "+l"(c) : "l"(a), "l"(b));
}
__device__ __forceinline__ unsigned long long pk2(float x) {
    unsigned long long r;
    asm("mov.b64 %0, {%1, %1};" : "=l"(r) : "f"(x));
    return r;
}
__device__ __forceinline__ float2 upk2(unsigned long long v) {
    float2 f;
    asm("mov.b64 {%0, %1}, %2;" : "=f"(f.x), "=f"(f.y) : "l"(v));
    return f;
}

__device__ __forceinline__ float to_tf32(float x) {
    float o;
    asm("cvt.rna.tf32.f32 %0, %1;" : "=f"(o) : "f"(x));
    return o;
}

// ---------------- CSR construction ----------------
__global__ void hist_kernel(const int* __restrict__ dst, int E) {
    int b = (blockIdx.x * blockDim.x + threadIdx.x) * 4;
    if (b + 3 < E) {
        int4 d = *(const int4*)(dst + b);
        atomicAdd(&g_cnt[d.x], 1);
        atomicAdd(&g_cnt[d.y], 1);
        atomicAdd(&g_cnt[d.z], 1);
        atomicAdd(&g_cnt[d.w], 1);
    } else {
        for (int e = b; e < E; e++) atomicAdd(&g_cnt[dst[e]], 1);
    }
}

__global__ void scan_kernel(int n, int E) {
    const int T = 1024;
    __shared__ int sh[T];
    int tid = threadIdx.x;
    int chunk = (n + T - 1) / T;
    int start = tid * chunk;
    int stop  = min(start + chunk, n);
    int sum = 0;
    for (int i = start; i < stop; i++) sum += g_cnt[i];
    sh[tid] = sum;
    __syncthreads();
    for (int off = 1; off < T; off <<= 1) {
        int v = (tid >= off) ? sh[tid - off] : 0;
        __syncthreads();
        sh[tid] += v;
        __syncthreads();
    }
    int run = sh[tid] - sum;
    for (int i = start; i < stop; i++) {
        g_rowptr[i] = run;
        g_cursor[i] = run;
        run += g_cnt[i];
    }
    if (tid == 0) g_rowptr[n] = E;
}

__global__ void scatter_kernel(const int* __restrict__ src, const int* __restrict__ dst, int E) {
    int b = (blockIdx.x * blockDim.x + threadIdx.x) * 4;
    if (b + 3 < E) {
        int4 s = *(const int4*)(src + b);
        int4 d = *(const int4*)(dst + b);
        int p0 = atomicAdd(&g_cursor[d.x], 1);
        int p1 = atomicAdd(&g_cursor[d.y], 1);
        int p2 = atomicAdd(&g_cursor[d.z], 1);
        int p3 = atomicAdd(&g_cursor[d.w], 1);
        g_csrc[p0] = s.x; g_csrc[p1] = s.y;
        g_csrc[p2] = s.z; g_csrc[p3] = s.w;
    } else {
        for (int e = b; e < E; e++) {
            int p = atomicAdd(&g_cursor[dst[e]], 1);
            g_csrc[p] = src[e];
        }
    }
}

// ---------------- tf32 tensor-core GEMM: out[n,F] = A[n,K] @ W[K,F] ----------------
template <int K, int F>
__global__ void gemmT_kernel(const float* __restrict__ A, const float* __restrict__ W,
                             float* __restrict__ out, int n) {
    static_assert(K % 4 == 0 && F % 4 == 0, "quad-aligned");
    __shared__ float As[2][16][132];
    __shared__ float Ws[2][16][72];
    const int t    = threadIdx.x;
    const int lane = t & 31;
    const int warp = t >> 5;
    const int wm = warp & 3;
    const int wn = warp >> 2;
    const int gid = lane >> 2, tig = lane & 3;
    const int m0 = blockIdx.x * 128;
    const int f0 = blockIdx.y * 64;
    const int KT = (K + 15) / 16;

    float acc[2][4][4];
#pragma unroll
    for (int ma = 0; ma < 2; ma++)
#pragma unroll
        for (int na = 0; na < 4; na++)
#pragma unroll
            for (int c = 0; c < 4; c++) acc[ma][na][c] = 0.f;

    float4 rA[2], rW;

    auto loadG = [&](int k0) {
#pragma unroll
        for (int i = 0; i < 2; i++) {
            int q = i * 256 + t;
            int m = q >> 2, kq = q & 3;
            int row = m0 + m, k = k0 + kq * 4;
            float4 v = make_float4(0.f, 0.f, 0.f, 0.f);
            if (row < n && k < K) v = *(const float4*)(A + (long)row * K + k);
            rA[i] = v;
        }
        {
            int krow = t >> 4, fq = t & 15;
            int k = k0 + krow, f = f0 + fq * 4;
            float4 v = make_float4(0.f, 0.f, 0.f, 0.f);
            if (k < K && f < F) v = *(const float4*)(W + (long)k * F + f);
            rW = v;
        }
    };
    auto storeS = [&](int s) {
#pragma unroll
        for (int i = 0; i < 2; i++) {
            int q = i * 256 + t;
            int m = q >> 2, kq = q & 3;
            As[s][kq * 4 + 0][m] = to_tf32(rA[i].x);
            As[s][kq * 4 + 1][m] = to_tf32(rA[i].y);
            As[s][kq * 4 + 2][m] = to_tf32(rA[i].z);
            As[s][kq * 4 + 3][m] = to_tf32(rA[i].w);
        }
        int krow = t >> 4, fq = t & 15;
        float4 w4 = make_float4(to_tf32(rW.x), to_tf32(rW.y), to_tf32(rW.z), to_tf32(rW.w));
        *(float4*)&Ws[s][krow][fq * 4] = w4;
    };

    loadG(0);
    storeS(0);
    __syncthreads();
    for (int ko = 0; ko < KT; ko++) {
        if (ko + 1 < KT) loadG((ko + 1) * 16);
        int s = ko & 1;
#pragma unroll
        for (int ka = 0; ka < 2; ka++) {
            int kk = ka * 8;
            unsigned a[2][4], b[4][2];
#pragma unroll
            for (int ma = 0; ma < 2; ma++) {
                int mrow = wm * 32 + ma * 16 + gid;
                a[ma][0] = __float_as_uint(As[s][kk + tig    ][mrow]);
                a[ma][1] = __float_as_uint(As[s][kk + tig    ][mrow + 8]);
                a[ma][2] = __float_as_uint(As[s][kk + tig + 4][mrow]);
                a[ma][3] = __float_as_uint(As[s][kk + tig + 4][mrow + 8]);
            }
#pragma unroll
            for (int na = 0; na < 4; na++) {
                int ncol = wn * 32 + na * 8 + gid;
                b[na][0] = __float_as_uint(Ws[s][kk + tig    ][ncol]);
                b[na][1] = __float_as_uint(Ws[s][kk + tig + 4][ncol]);
            }
#pragma unroll
            for (int ma = 0; ma < 2; ma++)
#pragma unroll
                for (int na = 0; na < 4; na++)
                    asm volatile(
                        "mma.sync.aligned.m16n8k8.row.col.f32.tf32.tf32.f32 "
                        "{%0,%1,%2,%3}, {%4,%5,%6,%7}, {%8,%9}, {%0,%1,%2,%3};"
                        : "+f"(acc[ma][na][0]), "+f"(acc[ma][na][1]),
                          "+f"(acc[ma][na][2]), "+f"(acc[ma][na][3])
                        : "r"(a[ma][0]), "r"(a[ma][1]), "r"(a[ma][2]), "r"(a[ma][3]),
                          "r"(b[na][0]), "r"(b[na][1]));
        }
        __syncthreads();
        if (ko + 1 < KT) {
            storeS((ko + 1) & 1);
            __syncthreads();
        }
    }

#pragma unroll
    for (int ma = 0; ma < 2; ma++) {
        int r0 = m0 + wm * 32 + ma * 16 + gid;
#pragma unroll
        for (int na = 0; na < 4; na++) {
            int c = f0 + wn * 32 + na * 8 + 2 * tig;
            if (c < F) {
                if (r0 < n) {
                    float2 v = make_float2(acc[ma][na][0], acc[ma][na][1]);
                    *(float2*)(out + (long)r0 * F + c) = v;
                }
                if (r0 + 8 < n) {
                    float2 v = make_float2(acc[ma][na][2], acc[ma][na][3]);
                    *(float2*)(out + (long)(r0 + 8) * F + c) = v;
                }
            }
        }
    }
}

// ---------------- el/er ----------------
__global__ void elr_kernel(const float* __restrict__ fs, const float* __restrict__ al,
                           const float* __restrict__ ar, int n, int Dd, int F) {
    int idx = blockIdx.x * blockDim.x + threadIdx.x;
    if (idx >= n * 4) return;
    int node = idx >> 2, h = idx & 3;
    const float* row = fs + node * F + h * Dd;
    const float* a1  = al + h * Dd;
    const float* a2  = ar + h * Dd;
    float se = 0.f, sr = 0.f;
#pragma unroll 8
    for (int d = 0; d < Dd; d++) {
        float v = row[d];
        se = fmaf(v, a1[d], se);
        sr = fmaf(v, a2[d], sr);
    }
    g_el[idx] = se;
    g_er[idx] = sr;
}

// ---------------- fused single-pass aggregation, F=128 (layers 0/1), unroll 8 -----------
__global__ void agg128_kernel(const float* __restrict__ fs, float* __restrict__ out,
                              int n, int dorelu) {
    int warp = (blockIdx.x * blockDim.x + threadIdx.x) >> 5;
    int lane = threadIdx.x & 31;
    if (warp >= n) return;
    int beg = g_rowptr[warp], end = g_rowptr[warp + 1];
    int h = lane >> 3;
    float er_h = g_er[warp * 4 + h];

    float s = 0.f;
    unsigned long long acc2[2] = {0ull, 0ull};
    int j = beg;
    for (; j + 8 <= end; j += 8) {
        int sc[8];
#pragma unroll
        for (int q = 0; q < 8; q++) sc[q] = g_csrc[j + q];
        float el[8];
#pragma unroll
        for (int q = 0; q < 8; q++) el[q] = g_el[sc[q] * 4 + h];
        ulonglong2 v[8];
#pragma unroll
        for (int q = 0; q < 8; q++) v[q] = *(const ulonglong2*)(fs + sc[q] * 128 + lane * 4);
#pragma unroll
        for (int q = 0; q < 8; q++) {
            float x = __expf(lrelu(el[q] + er_h));
            s += x;
            unsigned long long pa = pk2(x);
            ffma2(acc2[0], pa, v[q].x);
            ffma2(acc2[1], pa, v[q].y);
        }
    }
    for (; j < end; j++) {
        int sc = g_csrc[j];
        float x = __expf(lrelu(g_el[sc * 4 + h] + er_h));
        s += x;
        unsigned long long pa = pk2(x);
        ulonglong2 v = *(const ulonglong2*)(fs + sc * 128 + lane * 4);
        ffma2(acc2[0], pa, v.x);
        ffma2(acc2[1], pa, v.y);
    }
    float ish = s > 0.f ? 1.f / s : 0.f;
    float2 lo = upk2(acc2[0]);
    float2 hi = upk2(acc2[1]);
    float4 acc = make_float4(lo.x * ish, lo.y * ish, hi.x * ish, hi.y * ish);
    if (dorelu) {
        acc.x = fmaxf(acc.x, 0.f); acc.y = fmaxf(acc.y, 0.f);
        acc.z = fmaxf(acc.z, 0.f); acc.w = fmaxf(acc.w, 0.f);
    }
    *(float4*)(out + warp * 128 + lane * 4) = acc;
}

// ---------------- fused single-pass aggregation, F=188 (layer 2) ----------------
// 48 groups of 4 class-cols (12 per head). Lane g handles group lane (head gA/12);
// lanes 0-15 also handle group lane+32. <=2 exps per edge per lane.
// Guarded scalar loads for class cols >= 47 (incl. hA=3/cb=44 row overrun).
__global__ void agg188_kernel(const float* __restrict__ fs, float* __restrict__ out, int n) {
    int warp = (blockIdx.x * blockDim.x + threadIdx.x) >> 5;
    int lane = threadIdx.x & 31;
    if (warp >= n) return;
    int beg = g_rowptr[warp], end = g_rowptr[warp + 1];

    int gA = lane;
    int hA = gA / 12;
    int cbA = (gA - hA * 12) * 4;
    int baseA = hA * 47 + cbA;
    bool hasB = lane < 16;
    int gB = lane + 32;
    int hB = gB / 12;                 // 2..3
    int cbB = (gB - hB * 12) * 4;
    int baseB = hB * 47 + cbB;

    float erA = g_er[warp * 4 + hA];
    float erB = g_er[warp * 4 + (hasB ? hB : hA)];

    bool okA[4], okB[4];
#pragma unroll
    for (int i = 0; i < 4; i++) {
        okA[i] = (cbA + i) < 47;
        okB[i] = hasB && ((cbB + i) < 47);
    }

    float sA = 0.f, sB = 0.f;
    float accA[4] = {0.f, 0.f, 0.f, 0.f};
    float accB[4] = {0.f, 0.f, 0.f, 0.f};

    int j = beg;
    for (; j + 2 <= end; j += 2) {
        int sc0 = g_csrc[j];
        int sc1 = g_csrc[j + 1];
        float elA0 = g_el[sc0 * 4 + hA];
        float elA1 = g_el[sc1 * 4 + hA];
        float elB0 = hasB ? g_el[sc0 * 4 + hB] : 0.f;
        float elB1 = hasB ? g_el[sc1 * 4 + hB] : 0.f;
        const float* r0 = fs + (long)sc0 * 188;
        const float* r1 = fs + (long)sc1 * 188;
        float vA0[4], vA1[4], vB0[4], vB1[4];
#pragma unroll
        for (int i = 0; i < 4; i++) {
            vA0[i] = okA[i] ? r0[baseA + i] : 0.f;
            vA1[i] = okA[i] ? r1[baseA + i] : 0.f;
            vB0[i] = okB[i] ? r0[baseB + i] : 0.f;
            vB1[i] = okB[i] ? r1[baseB + i] : 0.f;
        }
        float xA0 = __expf(lrelu(elA0 + erA));
        float xA1 = __expf(lrelu(elA1 + erA));
        sA += xA0; sA += xA1;
#pragma unroll
        for (int i = 0; i < 4; i++) {
            accA[i] = fmaf(xA0, vA0[i], accA[i]);
            accA[i] = fmaf(xA1, vA1[i], accA[i]);
        }
        if (hasB) {
            float xB0 = __expf(lrelu(elB0 + erB));
            float xB1 = __expf(lrelu(elB1 + erB));
            sB += xB0; sB += xB1;
#pragma unroll
            for (int i = 0; i < 4; i++) {
                accB[i] = fmaf(xB0, vB0[i], accB[i]);
                accB[i] = fmaf(xB1, vB1[i], accB[i]);
            }
        }
    }
    if (j < end) {
        int sc = g_csrc[j];
        float elA = g_el[sc * 4 + hA];
        const float* r0 = fs + (long)sc * 188;
        float xA = __expf(lrelu(elA + erA));
        sA += xA;
#pragma unroll
        for (int i = 0; i < 4; i++)
            if (okA[i]) accA[i] = fmaf(xA, r0[baseA + i], accA[i]);
        if (hasB) {
            float xB = __expf(lrelu(g_el[sc * 4 + hB] + erB));
            sB += xB;
#pragma unroll
            for (int i = 0; i < 4; i++)
                if (okB[i]) accB[i] = fmaf(xB, r0[baseB + i], accB[i]);
        }
    }
    {
        float ish = sA > 0.f ? 1.f / sA : 0.f;
        float* po = out + (long)warp * 188 + baseA;
#pragma unroll
        for (int i = 0; i < 4; i++)
            if (okA[i]) po[i] = accA[i] * ish;
    }
    if (hasB) {
        float ish = sB > 0.f ? 1.f / sB : 0.f;
        float* po = out + (long)warp * 188 + baseB;
#pragma unroll
        for (int i = 0; i < 4; i++)
            if (okB[i]) po[i] = accB[i] * ish;
    }
}

// ---------------- head mean + log_softmax ----------------
__global__ void final_kernel(const float* __restrict__ o2, float* __restrict__ out, int n) {
    int warp = (blockIdx.x * blockDim.x + threadIdx.x) >> 5;
    int lane = threadIdx.x & 31;
    if (warp >= n) return;
    const float* base = o2 + warp * 188;
    int c1 = lane;
    int c2 = lane + 32;
    bool v2 = c2 < 47;
    float z1 = 0.25f * (base[c1] + base[47 + c1] + base[94 + c1] + base[141 + c1]);
    float z2 = v2 ? 0.25f * (base[c2] + base[47 + c2] + base[94 + c2] + base[141 + c2]) : -INFINITY;
    float mx = fmaxf(z1, z2);
#pragma unroll
    for (int off = 16; off; off >>= 1)
        mx = fmaxf(mx, __shfl_xor_sync(0xffffffffu, mx, off));
    float se = __expf(z1 - mx) + (v2 ? __expf(z2 - mx) : 0.f);
#pragma unroll
    for (int off = 16; off; off >>= 1)
        se += __shfl_xor_sync(0xffffffffu, se, off);
    float lse = mx + logf(se);
    out[warp * 47 + c1] = z1 - lse;
    if (v2) out[warp * 47 + c2] = z2 - lse;
}

// ---------------- driver ----------------
extern "C" void kernel_launch(void* const* d_in, const int* in_sizes, int n_in,
                              void* d_out, int out_size) {
    const float* x   = (const float*)d_in[0];
    const float* W0  = (const float*)d_in[1];
    const float* al0 = (const float*)d_in[2];
    const float* ar0 = (const float*)d_in[3];
    const float* W1  = (const float*)d_in[4];
    const float* al1 = (const float*)d_in[5];
    const float* ar1 = (const float*)d_in[6];
    const float* W2  = (const float*)d_in[7];
    const float* al2 = (const float*)d_in[8];
    const float* ar2 = (const float*)d_in[9];
    const int*   src = (const int*)d_in[10];
    const int*   dst = (const int*)d_in[11];
    int E = in_sizes[10];
    int N = in_sizes[0] / 100;
    float* out = (float*)d_out;

    float *fs, *a0, *a1, *o2;
    int* cnt;
    cudaGetSymbolAddress((void**)&fs, g_fs);
    cudaGetSymbolAddress((void**)&a0, g_act0);
    cudaGetSymbolAddress((void**)&a1, g_act1);
    cudaGetSymbolAddress((void**)&o2, g_out2);
    cudaGetSymbolAddress((void**)&cnt, g_cnt);

    static cudaStream_t s2 = 0;
    static cudaEvent_t evFork = 0, evJoin = 0;
    if (s2 == 0) {
        cudaStreamCreateWithFlags(&s2, cudaStreamNonBlocking);
        cudaEventCreateWithFlags(&evFork, cudaEventDisableTiming);
        cudaEventCreateWithFlags(&evJoin, cudaEventDisableTiming);
    }

    const int TB = 256;
    int e4bl = (E / 4 + TB - 1) / TB;
    int wbl = (N * 32 + TB - 1) / TB;
    int mbl = (N + 127) / 128;
    int lbl = (N * 4 + 127) / 128;

    // ---- fork: CSR construction on s2, concurrent with layer-0 gemm/elr ----
    cudaEventRecord(evFork, 0);
    cudaStreamWaitEvent(s2, evFork, 0);
    cudaMemsetAsync(cnt, 0, N * sizeof(int), s2);
    hist_kernel<<<e4bl, TB, 0, s2>>>(dst, E);
    scan_kernel<<<1, 1024, 0, s2>>>(N, E);
    scatter_kernel<<<e4bl, TB, 0, s2>>>(src, dst, E);
    cudaEventRecord(evJoin, s2);

    // Layer 0: x[N,100] -> fs[N,128] -> agg -> act0[N,128]
    gemmT_kernel<100, 128><<<dim3(mbl, 2), 256>>>(x, W0, fs, N);
    elr_kernel<<<lbl, 128>>>(fs, al0, ar0, N, 32, 128);
    cudaStreamWaitEvent(0, evJoin, 0);
    agg128_kernel<<<wbl, TB>>>(fs, a0, N, 1);

    // Layer 1
    gemmT_kernel<128, 128><<<dim3(mbl, 2), 256>>>(a0, W1, fs, N);
    elr_kernel<<<lbl, 128>>>(fs, al1, ar1, N, 32, 128);
    agg128_kernel<<<wbl, TB>>>(fs, a1, N, 1);

    // Layer 2
    gemmT_kernel<128, 188><<<dim3(mbl, 3), 256>>>(a1, W2, fs, N);
    elr_kernel<<<lbl, 128>>>(fs, al2, ar2, N, 47, 188);
    agg188_kernel<<<wbl, TB>>>(fs, o2, N);

    // head mean + log_softmax
    final_kernel<<<wbl, TB>>>(o2, out, N);
}